// round 15
// baseline (speedup 1.0000x reference)
#include <cuda_runtime.h>
#include <cuda_fp16.h>
#include <cstdint>

#define TPB   128
#define TPT   4        // tiles per warp
#define CTAS  2048     // 2048 CTAs * 4 warps * 4 tiles * 32 rows = 1,048,576
#define NL    5

// ---- smem byte offsets ----
#define SMB_WF  0                      // 5*24*32 * 16B = 61440  {Wh0,Wh1,Wl0,Wl1}
#define SMB_FCF (SMB_WF + 61440)       // 8*32 * 16B = 4096
#define SMB_B1  (SMB_FCF + 4096)       // 5*16 * 16B = 1280  {br0,br1,bz0,bz1}
#define SMB_B2  (SMB_B1 + 1280)        // 1280               {bn0,bn1,bh0,bh1}
#define SMB_FCB (SMB_B2 + 1280)        // 128
#define SMEM_BYTES (SMB_FCB + 128)     // 68224

// ---- helpers ----
// pack rn-rounded fp16 pair: x0 -> low half, x1 -> high half
__device__ __forceinline__ unsigned packh2(float x0, float x1) {
    unsigned r;
    asm("cvt.rn.f16x2.f32 %0, %1, %2;" : "=r"(r) : "f"(x1), "f"(x0));
    return r;
}
__device__ __forceinline__ void mma_f16(float d[4], const unsigned a[4],
                                        unsigned b0, unsigned b1) {
    asm volatile(
        "mma.sync.aligned.m16n8k16.row.col.f32.f16.f16.f32 "
        "{%0,%1,%2,%3}, {%4,%5,%6,%7}, {%8,%9}, {%0,%1,%2,%3};"
        : "+f"(d[0]), "+f"(d[1]), "+f"(d[2]), "+f"(d[3])
        : "r"(a[0]), "r"(a[1]), "r"(a[2]), "r"(a[3]), "r"(b0), "r"(b1));
}
__device__ __forceinline__ float tanha(float x) {
    float r; asm("tanh.approx.f32 %0, %1;" : "=f"(r) : "f"(x)); return r;
}
// sigmoid via hw tanh: 1 MUFU (0.5 factor halves tanh.approx abs error)
__device__ __forceinline__ float sigm_t(float x) {
    return fmaf(0.5f, tanha(0.5f * x), 0.5f);
}
// weight split: hi = rn(w) as fp16, lo = rn(w - hi)  (2-term, ~2^-21 residual)
__device__ __forceinline__ void wsplit(float2 w, unsigned& hi, unsigned& lo) {
    hi = packh2(w.x, w.y);
    const __half2 h2 = *(__half2*)&hi;
    lo = packh2(w.x - __low2float(h2), w.y - __high2float(h2));
}

__global__ void __launch_bounds__(TPB, 3) gru_mma(
    const float* __restrict__ x,    const float* __restrict__ w_ih,
    const float* __restrict__ b_ih, const float* __restrict__ b_hh,
    const float* __restrict__ fc_w, const float* __restrict__ fc_b,
    float* __restrict__ out)
{
    extern __shared__ char smem[];
    uint4*  WF  = (uint4*)(smem + SMB_WF);
    uint4*  FCF = (uint4*)(smem + SMB_FCF);
    float4* B1  = (float4*)(smem + SMB_B1);
    float4* B2  = (float4*)(smem + SMB_B2);
    float*  FCBs = (float*)(smem + SMB_FCB);

    const int tid  = threadIdx.x;
    const int lane = tid & 31;
    const int warp = tid >> 5;

    // ---- preload GRU weight fragments (B layout of m16n8k16.col per lane) ----
    for (int s = tid; s < NL * 2 * 12 * 32; s += TPB) {
        const int ln = s & 31;
        int q = s >> 5;
        const int nt = q % 12; q /= 12;
        const int kt = q & 1;
        const int l  = q >> 1;
        const int j  = nt * 8 + (ln >> 2);            // output row [0,96)
        const int k0 = kt * 16 + (ln & 3) * 2;        // k col pair
        const float* wr = w_ih + (l * 96 + j) * 32 + k0;
        unsigned h0, l0, h1, l1;
        wsplit(*(const float2*)(wr),     h0, l0);
        wsplit(*(const float2*)(wr + 8), h1, l1);
        WF[s] = make_uint4(h0, h1, l0, l1);
    }
    // ---- FC weight fragments ----
    for (int s = tid; s < 2 * 4 * 32; s += TPB) {
        const int ln = s & 31;
        const int q = s >> 5;
        const int nt = q & 3;
        const int kt = q >> 2;
        const int j  = nt * 8 + (ln >> 2);
        const int k0 = kt * 16 + (ln & 3) * 2;
        const float* wr = fc_w + j * 32 + k0;
        unsigned h0, l0, h1, l1;
        wsplit(*(const float2*)(wr),     h0, l0);
        wsplit(*(const float2*)(wr + 8), h1, l1);
        FCF[s] = make_uint4(h0, h1, l0, l1);
    }
    // ---- biases packed as float4 (h0==0: hh-path collapses to b_hh) ----
    for (int i = tid; i < NL * 16; i += TPB) {
        const int l = i >> 4, q = i & 15, nt = q >> 2, cpx = q & 3;
        const int j = nt * 8 + cpx * 2;
        B1[i] = make_float4(b_ih[l*96 + j]      + b_hh[l*96 + j],
                            b_ih[l*96 + j + 1]  + b_hh[l*96 + j + 1],
                            b_ih[l*96 + 32 + j]     + b_hh[l*96 + 32 + j],
                            b_ih[l*96 + 32 + j + 1] + b_hh[l*96 + 32 + j + 1]);
        B2[i] = make_float4(b_ih[l*96 + 64 + j], b_ih[l*96 + 64 + j + 1],
                            b_hh[l*96 + 64 + j], b_hh[l*96 + 64 + j + 1]);
    }
    if (tid < 32) FCBs[tid] = fc_b[tid];
    __syncthreads();

    const int lm4 = (lane & 3) * 2;   // column-pair base within n8/k16
    const int ld4 = lane >> 2;        // row offset within m16
    const int cp  = lane & 3;

    for (int t = 0; t < TPT; t++) {
        const int wtile = blockIdx.x * (4 * TPT) + t * 4 + warp;
        const size_t rowbase = (size_t)wtile * 32;

        unsigned A[2][2][4];          // single fp16 A fragments (no residual)
        // ---- x fragments straight from gmem ----
#pragma unroll
        for (int m = 0; m < 2; m++)
#pragma unroll
        for (int kt = 0; kt < 2; kt++) {
            const float* xb = x + (rowbase + m * 16 + ld4) * 32 + kt * 16 + lm4;
            const float2 v0 = *(const float2*)(xb);
            const float2 v1 = *(const float2*)(xb + 8 * 32);
            const float2 v2 = *(const float2*)(xb + 8);
            const float2 v3 = *(const float2*)(xb + 8 * 32 + 8);
            A[m][kt][0] = packh2(v0.x, v0.y);
            A[m][kt][1] = packh2(v1.x, v1.y);
            A[m][kt][2] = packh2(v2.x, v2.y);
            A[m][kt][3] = packh2(v3.x, v3.y);
        }

        // ---- 5 GRU layers, fully register-resident ----
#pragma unroll 1
        for (int l = 0; l < NL; l++) {
            float D[2][12][4];
            // accumulators init with gate biases (col-dependent only)
#pragma unroll
            for (int nt = 0; nt < 4; nt++) {
                const float4 bb = B1[(l * 4 + nt) * 4 + cp];
                const float4 b2 = B2[(l * 4 + nt) * 4 + cp];
#pragma unroll
                for (int m = 0; m < 2; m++) {
                    D[m][nt][0]   = bb.x; D[m][nt][1]   = bb.y;
                    D[m][nt][2]   = bb.x; D[m][nt][3]   = bb.y;
                    D[m][nt+4][0] = bb.z; D[m][nt+4][1] = bb.w;
                    D[m][nt+4][2] = bb.z; D[m][nt+4][3] = bb.w;
                    D[m][nt+8][0] = b2.x; D[m][nt+8][1] = b2.y;
                    D[m][nt+8][2] = b2.x; D[m][nt+8][3] = b2.y;
                }
            }
            const uint4* WL = WF + l * (2 * 12 * 32);
#pragma unroll
            for (int kt = 0; kt < 2; kt++)
#pragma unroll
            for (int nt = 0; nt < 12; nt++) {
                const uint4 f = WL[(kt * 12 + nt) * 32 + lane];
                mma_f16(D[0][nt], A[0][kt], f.x, f.y);   // A * W_hi
                mma_f16(D[1][nt], A[1][kt], f.x, f.y);
                mma_f16(D[0][nt], A[0][kt], f.z, f.w);   // A * W_lo
                mma_f16(D[1][nt], A[1][kt], f.z, f.w);
            }
            // gate epilogue -> next layer's A fragments (D layout == A layout)
#pragma unroll
            for (int tt = 0; tt < 4; tt++) {
                const float4 b2 = B2[(l * 4 + tt) * 4 + cp];   // .z,.w = bh pair
#pragma unroll
                for (int m = 0; m < 2; m++) {
#pragma unroll
                    for (int hf = 0; hf < 2; hf++) {
                        const float rr0 = sigm_t(D[m][tt][2*hf]);
                        const float rr1 = sigm_t(D[m][tt][2*hf+1]);
                        const float zz0 = sigm_t(D[m][tt+4][2*hf]);
                        const float zz1 = sigm_t(D[m][tt+4][2*hf+1]);
                        const float nn0 = tanha(D[m][tt+8][2*hf]   + rr0 * b2.z);
                        const float nn1 = tanha(D[m][tt+8][2*hf+1] + rr1 * b2.w);
                        const float h0 = fmaf(-zz0, nn0, nn0);
                        const float h1 = fmaf(-zz1, nn1, nn1);
                        A[m][tt >> 1][2*(tt & 1) + hf] = packh2(h0, h1);
                    }
                }
            }
        }

        // ---- FC: same 2-term MMA, N=32, bias in accum init ----
        float DF[2][4][4];
#pragma unroll
        for (int nt = 0; nt < 4; nt++) {
            const float2 fb2 = *(const float2*)(FCBs + nt * 8 + lm4);
#pragma unroll
            for (int m = 0; m < 2; m++) {
                DF[m][nt][0] = fb2.x; DF[m][nt][1] = fb2.y;
                DF[m][nt][2] = fb2.x; DF[m][nt][3] = fb2.y;
            }
        }
#pragma unroll
        for (int kt = 0; kt < 2; kt++)
#pragma unroll
        for (int nt = 0; nt < 4; nt++) {
            const uint4 f = FCF[(kt * 4 + nt) * 32 + lane];
            mma_f16(DF[0][nt], A[0][kt], f.x, f.y);
            mma_f16(DF[1][nt], A[1][kt], f.x, f.y);
            mma_f16(DF[0][nt], A[0][kt], f.z, f.w);
            mma_f16(DF[1][nt], A[1][kt], f.z, f.w);
        }
        // ---- store ----
#pragma unroll
        for (int m = 0; m < 2; m++)
#pragma unroll
        for (int nt = 0; nt < 4; nt++) {
            float* ob = out + (rowbase + m * 16 + ld4) * 32 + nt * 8 + lm4;
            *(float2*)(ob)          = make_float2(DF[m][nt][0], DF[m][nt][1]);
            *(float2*)(ob + 8 * 32) = make_float2(DF[m][nt][2], DF[m][nt][3]);
        }
    }
}

extern "C" void kernel_launch(void* const* d_in, const int* in_sizes, int n_in,
                              void* d_out, int out_size)
{
    const float* x    = (const float*)d_in[0];
    const float* w_ih = (const float*)d_in[1];
    // d_in[2] = w_hh: provably unused (h0 == 0 for every layer, T == 1)
    const float* b_ih = (const float*)d_in[3];
    const float* b_hh = (const float*)d_in[4];
    const float* fc_w = (const float*)d_in[5];
    const float* fc_b = (const float*)d_in[6];
    float* out = (float*)d_out;

    cudaFuncSetAttribute(gru_mma, cudaFuncAttributeMaxDynamicSharedMemorySize,
                         (int)SMEM_BYTES);
    gru_mma<<<CTAS, TPB, SMEM_BYTES>>>(x, w_ih, b_ih, b_hh, fc_w, fc_b, out);
}